// round 2
// baseline (speedup 1.0000x reference)
#include <cuda_runtime.h>
#include <math.h>

#define NLOC  2048
#define NTYPE 4
#define RCUT2 36.0f

// wrapped coords (xyz) + atom type (bits in .w)
__device__ float4 g_xw[NLOC];

// ---------------------------------------------------------------------------
// Kernel A: wrap coordinates into the box exactly like the reference:
//   frac = (x * (1/L)) mod 1 ;  xn = frac * L    (diagonal box)
// ---------------------------------------------------------------------------
__global__ void wrap_kernel(const float* __restrict__ coord,
                            const int*   __restrict__ atype,
                            const float* __restrict__ box) {
    int i = blockIdx.x * blockDim.x + threadIdx.x;
    if (i >= NLOC) return;
    float Lx = box[0], Ly = box[4], Lz = box[8];
    float fx = coord[i * 3 + 0] * (1.0f / Lx);
    float fy = coord[i * 3 + 1] * (1.0f / Ly);
    float fz = coord[i * 3 + 2] * (1.0f / Lz);
    fx -= floorf(fx);
    fy -= floorf(fy);
    fz -= floorf(fz);
    g_xw[i] = make_float4(fx * Lx, fy * Ly, fz * Lz, __int_as_float(atype[i]));
}

// ---------------------------------------------------------------------------
// Kernel B: one warp per local atom i. All-pairs min-image loop over j.
// Per hit (r2 < RCUT^2, j != i):
//   sw   = 0.5*(cos(pi*r/6)+1),  sw' = -0.5*(pi/6)*sin(pi*r/6)
//   atom_e_i += 0.5 * a[ti][tj] * sw / r
//   F_i += -0.5*(a[ti][tj]+a[tj][ti]) * (sw'/r - sw/r^2)/r * (xi-xj)
// (force coefficient is SYMMETRIZED: pair appears in both i's and j's
//  neighbor lists with transposed table entries)
// Warp shuffle reduction, lane 0 writes. No atomics -> deterministic.
// ---------------------------------------------------------------------------
#define WPB 8   // warps per block
__global__ __launch_bounds__(WPB * 32)
void pair_kernel(const float* __restrict__ box,
                 const float* __restrict__ table,
                 float* __restrict__ out) {
    const int lane = threadIdx.x & 31;
    const int i    = blockIdx.x * WPB + (threadIdx.x >> 5);

    const float Lx = box[0], Ly = box[4], Lz = box[8];
    const float iLx = 1.0f / Lx, iLy = 1.0f / Ly, iLz = 1.0f / Lz;

    const float4 pi4 = g_xw[i];
    const int ti = __float_as_int(pi4.w);
    // row ti (energy coefficient) and symmetrized coefficients (force)
    const float a0 = table[ti * NTYPE + 0];
    const float a1 = table[ti * NTYPE + 1];
    const float a2 = table[ti * NTYPE + 2];
    const float a3 = table[ti * NTYPE + 3];
    const float s0 = 0.5f * (a0 + table[0 * NTYPE + ti]);
    const float s1 = 0.5f * (a1 + table[1 * NTYPE + ti]);
    const float s2 = 0.5f * (a2 + table[2 * NTYPE + ti]);
    const float s3 = 0.5f * (a3 + table[3 * NTYPE + ti]);

    const float PI_OVER_R = 3.14159265358979323846f / 6.0f;

    float esum = 0.0f, fxs = 0.0f, fys = 0.0f, fzs = 0.0f;

    for (int j = lane; j < NLOC; j += 32) {
        float4 pj = g_xw[j];
        float dx = pi4.x - pj.x;
        float dy = pi4.y - pj.y;
        float dz = pi4.z - pj.z;
        // minimum image (wrap each component to [-L/2, L/2])
        dx -= Lx * rintf(dx * iLx);
        dy -= Ly * rintf(dy * iLy);
        dz -= Lz * rintf(dz * iLz);
        float r2 = dx * dx + dy * dy + dz * dz;

        if (r2 < RCUT2 && j != i) {
            float r    = sqrtf(r2 + 1e-12f);
            float rinv = 1.0f / r;
            int   tj   = __float_as_int(pj.w);
            float ae   = (tj == 0) ? a0 : (tj == 1) ? a1 : (tj == 2) ? a2 : a3;
            float af   = (tj == 0) ? s0 : (tj == 1) ? s1 : (tj == 2) ? s2 : s3;

            float t = PI_OVER_R * r;
            float s, c;
            sincosf(t, &s, &c);
            float sw  = 0.5f * (c + 1.0f);
            float swp = -0.5f * PI_OVER_R * s;

            esum += ae * sw * rinv;
            // force scale: -a_sym * (sw'/r - sw/r^2) / r
            float fs = -af * (swp * rinv - sw * rinv * rinv) * rinv;
            fxs += fs * dx;
            fys += fs * dy;
            fzs += fs * dz;
        }
    }

    // warp reduction
    #pragma unroll
    for (int off = 16; off > 0; off >>= 1) {
        esum += __shfl_xor_sync(0xFFFFFFFFu, esum, off);
        fxs  += __shfl_xor_sync(0xFFFFFFFFu, fxs, off);
        fys  += __shfl_xor_sync(0xFFFFFFFFu, fys, off);
        fzs  += __shfl_xor_sync(0xFFFFFFFFu, fzs, off);
    }

    if (lane == 0) {
        out[1 + i] = 0.5f * esum;                 // atom_energy
        float* force = out + 1 + NLOC;
        force[i * 3 + 0] = fxs;
        force[i * 3 + 1] = fys;
        force[i * 3 + 2] = fzs;
    }
}

// ---------------------------------------------------------------------------
// Kernel C: deterministic total-energy reduction (single block).
// ---------------------------------------------------------------------------
__global__ void energy_reduce_kernel(float* __restrict__ out) {
    __shared__ float sh[1024];
    int t = threadIdx.x;
    sh[t] = out[1 + t] + out[1 + t + 1024];
    __syncthreads();
    #pragma unroll
    for (int s = 512; s > 0; s >>= 1) {
        if (t < s) sh[t] += sh[t + s];
        __syncthreads();
    }
    if (t == 0) out[0] = sh[0];
}

// ---------------------------------------------------------------------------
extern "C" void kernel_launch(void* const* d_in, const int* in_sizes, int n_in,
                              void* d_out, int out_size) {
    const float* coord = (const float*)d_in[0];   // (1,2048,3)
    const int*   atype = (const int*)d_in[1];     // (1,2048)
    const float* box   = (const float*)d_in[2];   // (1,3,3)
    const float* table = (const float*)d_in[3];   // (4,4)
    float* out = (float*)d_out;                   // [E(1) | atom_e(2048) | force(2048*3)]

    wrap_kernel<<<(NLOC + 255) / 256, 256>>>(coord, atype, box);
    pair_kernel<<<NLOC / WPB, WPB * 32>>>(box, table, out);
    energy_reduce_kernel<<<1, 1024>>>(out);
}

// round 3
// speedup vs baseline: 1.6057x; 1.6057x over previous
#include <cuda_runtime.h>
#include <math.h>

#define NLOC    2048
#define NTYPE   4
#define RCUT2   36.0f
#define WPB     8                 // warps per block (atoms per block)
#define THREADS (WPB * 32)        // 256
#define NBLOCKS (NLOC / WPB)      // 256

__device__ float        g_partials[NBLOCKS];
__device__ unsigned int g_counter = 0;

// ---------------------------------------------------------------------------
// ONE fused kernel:
//  phase 1: every block wraps ALL atoms into its own smem tile
//  phase 2: one warp per atom i, all-pairs min-image loop over smem
//  phase 3: last-block pattern reduces total energy (deterministic tree)
// ---------------------------------------------------------------------------
__global__ __launch_bounds__(THREADS)
void fused_kernel(const float* __restrict__ coord,
                  const int*   __restrict__ atype,
                  const float* __restrict__ box,
                  const float* __restrict__ table,
                  float*       __restrict__ out) {
    __shared__ float4 sh[NLOC];        // 32 KB: wrapped coords + type
    __shared__ float  sh_red[THREADS]; // reduction scratch
    __shared__ bool   sh_last;

    const int tid = threadIdx.x;

    const float Lx = box[0], Ly = box[4], Lz = box[8];
    const float iLx = 1.0f / Lx, iLy = 1.0f / Ly, iLz = 1.0f / Lz;

    // ---- phase 1: wrap all atoms into shared (redundant per block) ----
    #pragma unroll
    for (int a = tid; a < NLOC; a += THREADS) {
        float fx = coord[3 * a + 0] * iLx;
        float fy = coord[3 * a + 1] * iLy;
        float fz = coord[3 * a + 2] * iLz;
        fx -= floorf(fx);
        fy -= floorf(fy);
        fz -= floorf(fz);
        sh[a] = make_float4(fx * Lx, fy * Ly, fz * Lz, __int_as_float(atype[a]));
    }
    __syncthreads();

    // ---- phase 2: pair loop, one warp per atom ----
    const int lane = tid & 31;
    const int w    = tid >> 5;
    const int i    = blockIdx.x * WPB + w;

    const float4 pi4 = sh[i];
    const int    ti  = __float_as_int(pi4.w);
    // row ti (energy) and symmetrized coefficients (force): the pair (i,j)
    // appears in both neighbor lists with transposed table entries.
    const float a0 = table[ti * NTYPE + 0];
    const float a1 = table[ti * NTYPE + 1];
    const float a2 = table[ti * NTYPE + 2];
    const float a3 = table[ti * NTYPE + 3];
    const float s0 = 0.5f * (a0 + table[0 * NTYPE + ti]);
    const float s1 = 0.5f * (a1 + table[1 * NTYPE + ti]);
    const float s2 = 0.5f * (a2 + table[2 * NTYPE + ti]);
    const float s3 = 0.5f * (a3 + table[3 * NTYPE + ti]);

    const float PI_OVER_R = 3.14159265358979323846f / 6.0f;

    float esum = 0.0f, fxs = 0.0f, fys = 0.0f, fzs = 0.0f;

    #pragma unroll 4
    for (int j = lane; j < NLOC; j += 32) {
        float4 pj = sh[j];
        float dx = pi4.x - pj.x;
        float dy = pi4.y - pj.y;
        float dz = pi4.z - pj.z;
        // minimum image
        dx -= Lx * rintf(dx * iLx);
        dy -= Ly * rintf(dy * iLy);
        dz -= Lz * rintf(dz * iLz);
        float r2 = dx * dx + dy * dy + dz * dz;

        if (r2 < RCUT2 && j != i) {
            float rinv = rsqrtf(r2 + 1e-12f);
            float r    = r2 * rinv;
            int   tj   = __float_as_int(pj.w);
            float ae   = (tj == 0) ? a0 : (tj == 1) ? a1 : (tj == 2) ? a2 : a3;
            float af   = (tj == 0) ? s0 : (tj == 1) ? s1 : (tj == 2) ? s2 : s3;

            float t = PI_OVER_R * r;
            float s, c;
            __sincosf(t, &s, &c);          // t in [0, pi]: fast path is accurate
            float sw  = 0.5f * (c + 1.0f);
            float swp = -0.5f * PI_OVER_R * s;

            esum += ae * sw * rinv;
            // force scale: -a_sym * (sw'/r - sw/r^2) / r
            float fs = -af * (swp * rinv - sw * rinv * rinv) * rinv;
            fxs += fs * dx;
            fys += fs * dy;
            fzs += fs * dz;
        }
    }

    // warp reduction (deterministic)
    #pragma unroll
    for (int off = 16; off > 0; off >>= 1) {
        esum += __shfl_xor_sync(0xFFFFFFFFu, esum, off);
        fxs  += __shfl_xor_sync(0xFFFFFFFFu, fxs, off);
        fys  += __shfl_xor_sync(0xFFFFFFFFu, fys, off);
        fzs  += __shfl_xor_sync(0xFFFFFFFFu, fzs, off);
    }

    if (lane == 0) {
        out[1 + i] = 0.5f * esum;          // atom_energy
        float* force = out + 1 + NLOC;
        force[i * 3 + 0] = fxs;
        force[i * 3 + 1] = fys;
        force[i * 3 + 2] = fzs;
        sh_red[w] = 0.5f * esum;           // block partial
    }
    __syncthreads();

    // ---- phase 3: total energy via last-block pattern ----
    if (tid == 0) {
        float p = 0.0f;
        #pragma unroll
        for (int k = 0; k < WPB; k++) p += sh_red[k];
        g_partials[blockIdx.x] = p;
        __threadfence();
        unsigned int old = atomicAdd(&g_counter, 1u);
        sh_last = (old == NBLOCKS - 1);
    }
    __syncthreads();

    if (sh_last) {
        __threadfence();
        volatile float* vp = g_partials;
        sh_red[tid] = vp[tid];             // NBLOCKS == THREADS == 256
        __syncthreads();
        #pragma unroll
        for (int s = THREADS / 2; s > 0; s >>= 1) {
            if (tid < s) sh_red[tid] += sh_red[tid + s];
            __syncthreads();
        }
        if (tid == 0) {
            out[0] = sh_red[0];
            g_counter = 0;                 // reset for next graph replay
        }
    }
}

// ---------------------------------------------------------------------------
extern "C" void kernel_launch(void* const* d_in, const int* in_sizes, int n_in,
                              void* d_out, int out_size) {
    const float* coord = (const float*)d_in[0];   // (1,2048,3)
    const int*   atype = (const int*)d_in[1];     // (1,2048)
    const float* box   = (const float*)d_in[2];   // (1,3,3)
    const float* table = (const float*)d_in[3];   // (4,4)
    float* out = (float*)d_out;                   // [E(1) | atom_e(2048) | force(2048*3)]

    fused_kernel<<<NBLOCKS, THREADS>>>(coord, atype, box, table, out);
}

// round 4
// speedup vs baseline: 1.7264x; 1.0751x over previous
#include <cuda_runtime.h>
#include <math.h>

#define NLOC    2048
#define NTYPE   4
#define RCUT2   36.0f
#define APB     4                 // atoms per block
#define WPB     (APB * 2)         // 2 warps per atom
#define THREADS (WPB * 32)        // 256
#define NBLOCKS (NLOC / APB)      // 512

__device__ float        g_partials[NBLOCKS];
__device__ unsigned int g_counter = 0;

// ---------------------------------------------------------------------------
// ONE fused kernel:
//  phase 1: every block wraps ALL atoms into its own smem tile
//  phase 2: TWO warps per atom i split the j-range (stride 64), all-pairs
//           min-image; cheap |dx| min-image for the reject test, exact signed
//           min-image recomputed only on hits
//  phase 3: deterministic partial combine + last-block total-energy reduce
// ---------------------------------------------------------------------------
__global__ __launch_bounds__(THREADS)
void fused_kernel(const float* __restrict__ coord,
                  const int*   __restrict__ atype,
                  const float* __restrict__ box,
                  const float* __restrict__ table,
                  float*       __restrict__ out) {
    __shared__ float4 sh[NLOC];          // 32 KB wrapped coords + type
    __shared__ float  sh_part[WPB][4];   // per-warp partials (e, fx, fy, fz)
    __shared__ float  sh_ae[APB];        // combined atom energies
    __shared__ float  sh_red[256];       // last-block reduction scratch
    __shared__ bool   sh_last;

    const int tid = threadIdx.x;

    const float Lx = box[0], Ly = box[4], Lz = box[8];
    const float iLx = 1.0f / Lx, iLy = 1.0f / Ly, iLz = 1.0f / Lz;

    // ---- phase 1: wrap all atoms into shared (redundant per block) ----
    #pragma unroll
    for (int a = tid; a < NLOC; a += THREADS) {
        float fx = coord[3 * a + 0] * iLx;
        float fy = coord[3 * a + 1] * iLy;
        float fz = coord[3 * a + 2] * iLz;
        fx -= floorf(fx);
        fy -= floorf(fy);
        fz -= floorf(fz);
        sh[a] = make_float4(fx * Lx, fy * Ly, fz * Lz, __int_as_float(atype[a]));
    }
    __syncthreads();

    // ---- phase 2: pair loop, two warps per atom ----
    const int lane = tid & 31;
    const int w    = tid >> 5;          // warp in block
    const int a    = w >> 1;            // local atom
    const int half = w & 1;             // which half of the j range
    const int i    = blockIdx.x * APB + a;

    const float4 pi4 = sh[i];
    const int    ti  = __float_as_int(pi4.w);
    // row ti (energy) and symmetrized coefficients (force): the pair (i,j)
    // appears in both neighbor lists with transposed table entries.
    const float a0 = table[ti * NTYPE + 0];
    const float a1 = table[ti * NTYPE + 1];
    const float a2 = table[ti * NTYPE + 2];
    const float a3 = table[ti * NTYPE + 3];
    const float s0 = 0.5f * (a0 + table[0 * NTYPE + ti]);
    const float s1 = 0.5f * (a1 + table[1 * NTYPE + ti]);
    const float s2 = 0.5f * (a2 + table[2 * NTYPE + ti]);
    const float s3 = 0.5f * (a3 + table[3 * NTYPE + ti]);

    const float PI_OVER_R = 3.14159265358979323846f / 6.0f;

    float esum = 0.0f, fxs = 0.0f, fys = 0.0f, fzs = 0.0f;

    #pragma unroll 4
    for (int j = lane + 32 * half; j < NLOC; j += 64) {
        float4 pj = sh[j];
        float dx = pi4.x - pj.x;
        float dy = pi4.y - pj.y;
        float dz = pi4.z - pj.z;
        // magnitude-only min image (cheap reject):  m = min(|d|, L-|d|)
        float ax = fabsf(dx), ay = fabsf(dy), az = fabsf(dz);
        float mx = fminf(ax, Lx - ax);
        float my = fminf(ay, Ly - ay);
        float mz = fminf(az, Lz - az);
        float r2 = mx * mx + my * my + mz * mz;

        if (r2 < RCUT2 && r2 > 0.0f) {   // r2==0 only for the self pair
            float rinv = rsqrtf(r2 + 1e-12f);
            float r    = r2 * rinv;
            int   tj   = __float_as_int(pj.w);
            float ae   = (tj == 0) ? a0 : (tj == 1) ? a1 : (tj == 2) ? a2 : a3;
            float af   = (tj == 0) ? s0 : (tj == 1) ? s1 : (tj == 2) ? s2 : s3;

            float t = PI_OVER_R * r;
            float s, c;
            __sincosf(t, &s, &c);        // t in [0, pi]: fast path accurate
            float sw  = 0.5f * (c + 1.0f);
            float swp = -0.5f * PI_OVER_R * s;

            esum += ae * sw * rinv;

            // exact signed min-image (rare path)
            dx -= Lx * rintf(dx * iLx);
            dy -= Ly * rintf(dy * iLy);
            dz -= Lz * rintf(dz * iLz);

            // force scale: -a_sym * (sw'/r - sw/r^2) / r
            float fs = -af * (swp * rinv - sw * rinv * rinv) * rinv;
            fxs += fs * dx;
            fys += fs * dy;
            fzs += fs * dz;
        }
    }

    // warp reduction (deterministic)
    #pragma unroll
    for (int off = 16; off > 0; off >>= 1) {
        esum += __shfl_xor_sync(0xFFFFFFFFu, esum, off);
        fxs  += __shfl_xor_sync(0xFFFFFFFFu, fxs, off);
        fys  += __shfl_xor_sync(0xFFFFFFFFu, fys, off);
        fzs  += __shfl_xor_sync(0xFFFFFFFFu, fzs, off);
    }
    if (lane == 0) {
        sh_part[w][0] = esum;
        sh_part[w][1] = fxs;
        sh_part[w][2] = fys;
        sh_part[w][3] = fzs;
    }
    __syncthreads();

    // combine the two half-warps per atom, write outputs (fixed order)
    if (tid < APB * 4) {
        int aa = tid >> 2, c = tid & 3;
        float v = sh_part[2 * aa][c] + sh_part[2 * aa + 1][c];
        int ig = blockIdx.x * APB + aa;
        if (c == 0) {
            float e = 0.5f * v;
            out[1 + ig] = e;            // atom_energy
            sh_ae[aa] = e;
        } else {
            float* force = out + 1 + NLOC;
            force[ig * 3 + (c - 1)] = v;
        }
    }
    __syncthreads();

    // ---- phase 3: total energy via last-block pattern ----
    if (tid == 0) {
        float p = sh_ae[0] + sh_ae[1] + sh_ae[2] + sh_ae[3];
        g_partials[blockIdx.x] = p;
        __threadfence();
        unsigned int old = atomicAdd(&g_counter, 1u);
        sh_last = (old == NBLOCKS - 1);
    }
    __syncthreads();

    if (sh_last) {
        __threadfence();
        volatile float* vp = g_partials;
        sh_red[tid] = vp[tid] + vp[tid + 256];   // NBLOCKS == 512
        __syncthreads();
        #pragma unroll
        for (int s = 128; s > 0; s >>= 1) {
            if (tid < s) sh_red[tid] += sh_red[tid + s];
            __syncthreads();
        }
        if (tid == 0) {
            out[0] = sh_red[0];
            g_counter = 0;               // reset for next graph replay
        }
    }
}

// ---------------------------------------------------------------------------
extern "C" void kernel_launch(void* const* d_in, const int* in_sizes, int n_in,
                              void* d_out, int out_size) {
    const float* coord = (const float*)d_in[0];   // (1,2048,3)
    const int*   atype = (const int*)d_in[1];     // (1,2048)
    const float* box   = (const float*)d_in[2];   // (1,3,3)
    const float* table = (const float*)d_in[3];   // (4,4)
    float* out = (float*)d_out;                   // [E(1) | atom_e(2048) | force(2048*3)]

    fused_kernel<<<NBLOCKS, THREADS>>>(coord, atype, box, table, out);
}

// round 5
// speedup vs baseline: 1.8589x; 1.0768x over previous
#include <cuda_runtime.h>
#include <math.h>

#define NLOC    2048
#define NTYPE   4
#define RCUT2   36.0f
#define APB     8                 // atoms per block
#define WPA     4                 // warps per atom
#define WPB     (APB * WPA)       // 32 warps
#define THREADS (WPB * 32)        // 1024
#define NBLOCKS (NLOC / APB)      // 256

__device__ float        g_partials[NBLOCKS];
__device__ unsigned int g_counter = 0;

// ---------------------------------------------------------------------------
// ONE fused kernel:
//  phase 1: every block wraps ALL atoms into its own smem tile
//  phase 2: FOUR warps per atom i split the j-range (stride 128); cheap
//           magnitude-only min-image for the reject test; signed component
//           recovered on hits via copysign trick (no rintf)
//  phase 3: deterministic 4-way combine + last-block total-energy reduce
// ---------------------------------------------------------------------------
__global__ __launch_bounds__(THREADS)
void fused_kernel(const float* __restrict__ coord,
                  const int*   __restrict__ atype,
                  const float* __restrict__ box,
                  const float* __restrict__ table,
                  float*       __restrict__ out) {
    __shared__ float4 sh[NLOC];          // 32 KB wrapped coords + type
    __shared__ float  sh_part[WPB][4];   // per-warp partials (e, fx, fy, fz)
    __shared__ float  sh_ae[APB];        // combined atom energies
    __shared__ float  sh_red[256];       // last-block reduction scratch
    __shared__ bool   sh_last;

    const int tid = threadIdx.x;

    const float Lx = box[0], Ly = box[4], Lz = box[8];
    const float iLx = 1.0f / Lx, iLy = 1.0f / Ly, iLz = 1.0f / Lz;
    const float Hx = 0.5f * Lx, Hy = 0.5f * Ly, Hz = 0.5f * Lz;

    // ---- phase 1: wrap all atoms into shared (redundant per block) ----
    #pragma unroll
    for (int a = tid; a < NLOC; a += THREADS) {
        float fx = __ldg(&coord[3 * a + 0]) * iLx;
        float fy = __ldg(&coord[3 * a + 1]) * iLy;
        float fz = __ldg(&coord[3 * a + 2]) * iLz;
        fx -= floorf(fx);
        fy -= floorf(fy);
        fz -= floorf(fz);
        sh[a] = make_float4(fx * Lx, fy * Ly, fz * Lz, __int_as_float(atype[a]));
    }
    __syncthreads();

    // ---- phase 2: pair loop, four warps per atom ----
    const int lane = tid & 31;
    const int w    = tid >> 5;          // warp in block (0..31)
    const int a    = w >> 2;            // local atom (0..7)
    const int q    = w & 3;             // quarter of the j range
    const int i    = blockIdx.x * APB + a;

    const float4 pi4 = sh[i];
    const int    ti  = __float_as_int(pi4.w);
    // row ti (energy) and symmetrized coefficients (force): the pair (i,j)
    // appears in both neighbor lists with transposed table entries.
    const float a0 = table[ti * NTYPE + 0];
    const float a1 = table[ti * NTYPE + 1];
    const float a2 = table[ti * NTYPE + 2];
    const float a3 = table[ti * NTYPE + 3];
    const float s0 = 0.5f * (a0 + table[0 * NTYPE + ti]);
    const float s1 = 0.5f * (a1 + table[1 * NTYPE + ti]);
    const float s2 = 0.5f * (a2 + table[2 * NTYPE + ti]);
    const float s3 = 0.5f * (a3 + table[3 * NTYPE + ti]);

    const float PI_OVER_R = 3.14159265358979323846f / 6.0f;

    float esum = 0.0f, fxs = 0.0f, fys = 0.0f, fzs = 0.0f;

    #pragma unroll 4
    for (int j = lane + 32 * q; j < NLOC; j += 32 * WPA) {
        float4 pj = sh[j];
        float dx = pi4.x - pj.x;
        float dy = pi4.y - pj.y;
        float dz = pi4.z - pj.z;
        // magnitude-only min image:  m = min(|d|, L-|d|)
        float ax = fabsf(dx), ay = fabsf(dy), az = fabsf(dz);
        float mx = fminf(ax, Lx - ax);
        float my = fminf(ay, Ly - ay);
        float mz = fminf(az, Lz - az);
        float r2 = mx * mx + my * my + mz * mz;

        if (r2 < RCUT2 && r2 > 0.0f) {   // r2==0 only for the self pair
            float rinv = rsqrtf(r2 + 1e-12f);
            float r    = r2 * rinv;
            int   tj   = __float_as_int(pj.w);
            float ae   = (tj == 0) ? a0 : (tj == 1) ? a1 : (tj == 2) ? a2 : a3;
            float af   = (tj == 0) ? s0 : (tj == 1) ? s1 : (tj == 2) ? s2 : s3;

            float t = PI_OVER_R * r;
            float s, c;
            __sincosf(t, &s, &c);        // t in [0, pi]: fast path accurate
            float sw  = 0.5f * (c + 1.0f);
            float swp = -0.5f * PI_OVER_R * s;

            esum += ae * sw * rinv;

            // signed min-image from magnitude: sign flips iff |d| > L-|d|
            float sx = copysignf(mx, (Hx - ax) * dx);
            float sy = copysignf(my, (Hy - ay) * dy);
            float sz = copysignf(mz, (Hz - az) * dz);

            // force scale: -a_sym * (sw'/r - sw/r^2) / r
            float fs = -af * (swp * rinv - sw * rinv * rinv) * rinv;
            fxs += fs * sx;
            fys += fs * sy;
            fzs += fs * sz;
        }
    }

    // warp reduction (deterministic)
    #pragma unroll
    for (int off = 16; off > 0; off >>= 1) {
        esum += __shfl_xor_sync(0xFFFFFFFFu, esum, off);
        fxs  += __shfl_xor_sync(0xFFFFFFFFu, fxs, off);
        fys  += __shfl_xor_sync(0xFFFFFFFFu, fys, off);
        fzs  += __shfl_xor_sync(0xFFFFFFFFu, fzs, off);
    }
    if (lane == 0) {
        sh_part[w][0] = esum;
        sh_part[w][1] = fxs;
        sh_part[w][2] = fys;
        sh_part[w][3] = fzs;
    }
    __syncthreads();

    // combine the WPA warp-partials per atom in fixed order, write outputs
    if (tid < APB * 4) {
        int aa = tid >> 2, c = tid & 3;
        float v = sh_part[WPA * aa][c];
        #pragma unroll
        for (int k = 1; k < WPA; k++) v += sh_part[WPA * aa + k][c];
        int ig = blockIdx.x * APB + aa;
        if (c == 0) {
            float e = 0.5f * v;
            out[1 + ig] = e;            // atom_energy
            sh_ae[aa] = e;
        } else {
            float* force = out + 1 + NLOC;
            force[ig * 3 + (c - 1)] = v;
        }
    }
    __syncthreads();

    // ---- phase 3: total energy via last-block pattern ----
    if (tid == 0) {
        float p = 0.0f;
        #pragma unroll
        for (int k = 0; k < APB; k++) p += sh_ae[k];
        g_partials[blockIdx.x] = p;
        __threadfence();
        unsigned int old = atomicAdd(&g_counter, 1u);
        sh_last = (old == NBLOCKS - 1);
    }
    __syncthreads();

    if (sh_last) {
        __threadfence();
        if (tid < 256) {
            volatile float* vp = g_partials;
            sh_red[tid] = vp[tid];       // NBLOCKS == 256
        }
        __syncthreads();
        #pragma unroll
        for (int s = 128; s > 0; s >>= 1) {
            if (tid < s) sh_red[tid] += sh_red[tid + s];
            __syncthreads();
        }
        if (tid == 0) {
            out[0] = sh_red[0];
            g_counter = 0;               // reset for next graph replay
        }
    }
}

// ---------------------------------------------------------------------------
extern "C" void kernel_launch(void* const* d_in, const int* in_sizes, int n_in,
                              void* d_out, int out_size) {
    const float* coord = (const float*)d_in[0];   // (1,2048,3)
    const int*   atype = (const int*)d_in[1];     // (1,2048)
    const float* box   = (const float*)d_in[2];   // (1,3,3)
    const float* table = (const float*)d_in[3];   // (4,4)
    float* out = (float*)d_out;                   // [E(1) | atom_e(2048) | force(2048*3)]

    fused_kernel<<<NBLOCKS, THREADS>>>(coord, atype, box, table, out);
}